// round 15
// baseline (speedup 1.0000x reference)
#include <cuda_runtime.h>
#include <cuda_fp16.h>

#define BB 64
#define SS 512
#define II 1024
#define HH 1024
#define NG 4096          // 4*H
#define MMR (BB*SS)      // 32768
#define NCTA 128
#define PTHR 512

// ---------------- device scratch (no allocs allowed) ----------------
__device__ __align__(16) __half g_Uph[(size_t)NG * II];     // U_all^T [n][k], fp16
__device__ __align__(16) __half g_Wph[(size_t)NG * HH];     // W_all^T [n][k], fp16
// x fp16 in a-fragment order per step: uint2 g_xf[s][ (kk16*64 + row)*4 + tq ]
__device__ __align__(16) uint2 g_xf[(size_t)SS * 16384];
// h fp16 in a-fragment order (same convention), double buffered
__device__ __align__(16) unsigned g_hf[2][32768];
// two-level grid barrier: 8 group counters (128B-strided) -> root -> broadcast gen
__device__ unsigned g_cnt1[8 * 32];
__device__ unsigned g_cnt2;
__device__ unsigned g_gen;

// ---------------- helpers ----------------
__device__ __forceinline__ unsigned h2pack(float lo, float hi) {
    unsigned u;
    asm("cvt.rn.f16x2.f32 %0, %1, %2;" : "=r"(u) : "f"(hi), "f"(lo));
    return u;
}

__device__ __forceinline__ void mma16(float* d, const unsigned* a, unsigned b0, unsigned b1) {
    asm volatile(
        "mma.sync.aligned.m16n8k16.row.col.f32.f16.f16.f32 "
        "{%0,%1,%2,%3}, {%4,%5,%6,%7}, {%8,%9}, {%0,%1,%2,%3};"
        : "+f"(d[0]), "+f"(d[1]), "+f"(d[2]), "+f"(d[3])
        : "r"(a[0]), "r"(a[1]), "r"(a[2]), "r"(a[3]), "r"(b0), "r"(b1));
}

__device__ __forceinline__ float sigmf(float x) { return 1.f / (1.f + __expf(-x)); }

__device__ __forceinline__ void st_h_cg(__half* p, __half v) {
    unsigned short s = __half_as_ushort(v);
    asm volatile("st.global.cg.u16 [%0], %1;" :: "l"(p), "h"(s) : "memory");
}

__device__ __forceinline__ unsigned ld_acq(const unsigned* p) {
    unsigned v;
    asm volatile("ld.acquire.gpu.global.u32 %0, [%1];" : "=r"(v) : "l"(p) : "memory");
    return v;
}

__device__ __forceinline__ unsigned atom_add_acqrel(unsigned* p, unsigned v) {
    unsigned old;
    asm volatile("atom.add.acq_rel.gpu.global.u32 %0, [%1], %2;"
                 : "=r"(old) : "l"(p), "r"(v) : "memory");
    return old;
}

__device__ __forceinline__ void st_rel(unsigned* p, unsigned v) {
    asm volatile("st.release.gpu.global.u32 [%0], %1;" :: "l"(p), "r"(v) : "memory");
}

// named barriers: 0 = joint (512 thr, redX handoff), 1 = h-group (256 thr)
#define BARJ() asm volatile("bar.sync 0, 512;" ::: "memory")
#define BARH() asm volatile("bar.sync 1, 256;" ::: "memory")

// ---------------- pack: build K-major fp16 U_all^T / W_all^T ----------------
__global__ void pack_kernel(
    const float* __restrict__ Uf, const float* __restrict__ Ui,
    const float* __restrict__ Uc, const float* __restrict__ Uo,
    const float* __restrict__ Wf, const float* __restrict__ Wi,
    const float* __restrict__ Wc, const float* __restrict__ Wo)
{
    __shared__ float t[32][33];
    int z = blockIdx.z;
    int g = z & 3;
    const float* src;
    __half* dst;
    if (z < 4) { src = (g == 0) ? Uf : (g == 1) ? Ui : (g == 2) ? Uc : Uo; dst = g_Uph; }
    else       { src = (g == 0) ? Wf : (g == 1) ? Wi : (g == 2) ? Wc : Wo; dst = g_Wph; }
    int n0 = blockIdx.x * 32, k0 = blockIdx.y * 32;
    int tx = threadIdx.x, ty = threadIdx.y;   // 32 x 8
    #pragma unroll
    for (int i = 0; i < 4; i++) {
        int kr = ty + i * 8;
        t[kr][tx] = src[(size_t)(k0 + kr) * HH + n0 + tx];
    }
    __syncthreads();
    #pragma unroll
    for (int i = 0; i < 4; i++) {
        int nr = ty + i * 8;
        dst[(size_t)(g * HH + n0 + nr) * II + k0 + tx] = __float2half_rn(t[tx][nr]);
    }
}

// ---------------- x fp32 -> fp16 a-fragment order ----------------
// Job space: SS*16384 = 2^23 jobs, one uint2 each. idx bits: tq(2)|row(6)|kk(6)|s(9)
__global__ void xconv_kernel(const float* __restrict__ x) {
    int idx = blockIdx.x * 256 + threadIdx.x;
    if (idx >= SS * 16384) return;
    int tq  = idx & 3;
    int row = (idx >> 2) & 63;
    int kk  = (idx >> 8) & 63;
    int s   = idx >> 14;
    const float* xr = x + ((size_t)row * SS + s) * II + kk * 16;
    float2 lo = *(const float2*)(xr + 2 * tq);
    float2 hi = *(const float2*)(xr + 2 * tq + 8);
    g_xf[(size_t)s * 16384 + (kk * 64 + row) * 4 + tq] =
        make_uint2(h2pack(lo.x, lo.y), h2pack(hi.x, hi.y));
}

__global__ void init_kernel() {
    int i = blockIdx.x * blockDim.x + threadIdx.x;
    if (i < 32768) g_hf[0][i] = 0u;
    if (i < 8 * 32) g_cnt1[i] = 0u;
    if (i == 0) { g_cnt2 = 0u; g_gen = 0u; }
}

// ---------------- fused persistent kernel (warp-specialized) ----------------
// 128 CTAs x 512 thr. Warps 0-7: h-GEMM + reduce + gates + grid barrier.
// Warps 8-15: xp-GEMM for step s+1 (independent of barrier), dump into redX[(s+1)&1].
// Each group: 4 m-slabs(16 rows) x 2 K-splits(512), 128 mma/warp/step.
#define SM_W_BYTES   65536
#define SM_U_BASE    65536
#define RED_BASE     131072
#define RED_NP       5                          // float4 slots per (warp,lane), 1 pad
#define RED_SEG      20480                      // 8 warps * 32 * RED_NP * 16
#define SM_TOTAL     (RED_BASE + 3 * RED_SEG)   // 192512

__global__ __launch_bounds__(PTHR, 1) void lstm_persistent(
    float* __restrict__ out, float* __restrict__ out_hs,
    const float* __restrict__ bf, const float* __restrict__ bi,
    const float* __restrict__ bc, const float* __restrict__ bo)
{
    extern __shared__ __align__(16) unsigned char sm_raw[];
    float4* redH  = (float4*)(sm_raw + RED_BASE);
    float4* redX0 = (float4*)(sm_raw + RED_BASE + RED_SEG);
    float4* redX1 = (float4*)(sm_raw + RED_BASE + 2 * RED_SEG);

    const int tid = threadIdx.x;
    const int lane = tid & 31, w = tid >> 5;
    const int wq = w & 7;                      // group-local warp id
    const int wm = wq & 3, ks = wq >> 2;       // 4 m-slabs x 2 K-splits
    const int gq = lane >> 2, tq = lane & 3;
    const int j = blockIdx.x;

    // ---- one-time: pack W and U slices into swizzled fp16 fragment layout ----
    #pragma unroll
    for (int src = 0; src < 2; src++) {
        const unsigned* Wp_u = (const unsigned*)(src == 0 ? g_Wph : g_Uph);
        unsigned obase = src == 0 ? 0u : (unsigned)SM_U_BASE;
        #pragma unroll
        for (int t = 0; t < 8; t++) {
            int job = tid + t * PTHR;        // 4096 jobs = 64 kk16 x 32 slots x 2 chunks
            int kk = job >> 6;
            int rem = job & 63;
            int s  = rem >> 1, chunk = rem & 1;
            int sgq = s >> 2, stq = s & 3;
            int gp = chunk * 2;
            const unsigned* W0 = Wp_u + (size_t)(gp * 1024 + j * 8 + sgq) * 512;
            const unsigned* W1 = W0 + 1024 * 512;
            unsigned lo0 = W0[kk * 8 + stq], hi0 = W0[kk * 8 + stq + 4];
            unsigned lo1 = W1[kk * 8 + stq], hi1 = W1[kk * 8 + stq + 4];
            unsigned swz = ((unsigned)(s >> 2) & 1u) * 16u;
            unsigned off = obase + (unsigned)kk * 1024u +
                           (((unsigned)s * 32u + (unsigned)chunk * 16u) ^ swz);
            *(uint4*)(sm_raw + off) = make_uint4(lo0, hi0, lo1, hi1);
        }
    }
    __syncthreads();

    // per-thread b-frag smem offsets (swizzled)
    const int s_me = gq * 4 + tq;
    const unsigned swz_me = ((unsigned)(s_me >> 2) & 1u) * 16u;
    const unsigned woff0 = (((unsigned)s_me * 32u) ^ swz_me);
    const unsigned woff1 = (((unsigned)s_me * 32u + 16u) ^ swz_me);

    const int kb16 = ks * 32;                  // 32 kk16 slices per warp
    const int arow = wm * 16 + gq;             // a-frag row
    const int grp = j >> 4;                    // grid barrier group

    // 32-slice GEMM into acc: XB = a-frag base ptr (uint2*), WBASE = smem operand base
    #define GEMM32(XB, LDFN, WBASE)                                                \
    {                                                                              \
        uint2 qA[4][2];                                                            \
        _Pragma("unroll")                                                          \
        for (int p = 0; p < 4; p++) {                                              \
            int base = ((kb16 + p) * 64 + arow) * 4 + tq;                          \
            qA[p][0] = LDFN((XB) + base);                                          \
            qA[p][1] = LDFN((XB) + base + 32);                                     \
        }                                                                          \
        _Pragma("unroll 4")                                                        \
        for (int i = 0; i < 32; i++) {                                             \
            int sl = i & 3;                                                        \
            uint2 u0 = qA[sl][0], u1 = qA[sl][1];                                  \
            if (i < 28) {                                                          \
                int base = ((kb16 + i + 4) * 64 + arow) * 4 + tq;                  \
                qA[sl][0] = LDFN((XB) + base);                                     \
                qA[sl][1] = LDFN((XB) + base + 32);                                \
            }                                                                      \
            unsigned a0[4] = { u0.x, u1.x, u0.y, u1.y };                           \
            unsigned wb = (unsigned)(WBASE) + (unsigned)(kb16 + i) * 1024u;        \
            uint4 b01 = *(const uint4*)(sm_raw + wb + woff0);                      \
            uint4 b23 = *(const uint4*)(sm_raw + wb + woff1);                      \
            mma16(acc[0], a0, b01.x, b01.y);                                       \
            mma16(acc[1], a0, b01.z, b01.w);                                       \
            mma16(acc[2], a0, b23.x, b23.y);                                       \
            mma16(acc[3], a0, b23.z, b23.w);                                       \
        }                                                                          \
    }

    if (w < 8) {
        // ================= h-group =================
        const int cc = tid & 7;
        const int rrow = tid >> 3;                       // 0..31; 2nd output = rrow+32
        const int r_p  = ((rrow >> 3) & 1) * 2 + (cc & 1);
        const int r_lane = (rrow & 7) * 4 + (cc >> 1);
        const int r_wm0 = rrow >> 4;                     // 0..1
        const int r_wm1 = r_wm0 + 2;
        const int colg = j * 8 + cc;
        const int kkj = j >> 1;
        const int hidx0 = (((kkj * 64 + rrow) * 4 + (cc >> 1)) * 2 + (j & 1)) * 2 + (cc & 1);
        const int hidx1 = (((kkj * 64 + rrow + 32) * 4 + (cc >> 1)) * 2 + (j & 1)) * 2 + (cc & 1);
        const float bias0 = __ldg(bf + colg), bias1 = __ldg(bi + colg);
        const float bias2 = __ldg(bc + colg), bias3 = __ldg(bo + colg);
        float creg0 = 0.f, creg1 = 0.f;

        BARJ();   // matches xp prologue dump of redX[0]

        for (int s = 0; s < SS; s++) {
            if (tid == 0 && s > 0) {
                while (ld_acq(&g_gen) < (unsigned)s) { }
            }
            BARH();                                       // release h-group for step s

            const uint2* __restrict__ hb = (const uint2*)g_hf[s & 1];
            __half*      __restrict__ hw = (__half*)g_hf[(s + 1) & 1];

            float acc[4][4];
            #pragma unroll
            for (int g = 0; g < 4; g++)
                #pragma unroll
                for (int p = 0; p < 4; p++) acc[g][p] = 0.f;

            GEMM32(hb, __ldcg, 0u);

            {   // dump h partials
                float4* dst4 = redH + (wq * 32 + lane) * RED_NP;
                #pragma unroll
                for (int p = 0; p < 4; p++)
                    dst4[p] = make_float4(acc[0][p], acc[1][p], acc[2][p], acc[3][p]);
            }
            BARH();

            const float4* redX = (s & 1) ? redX1 : redX0;

            // reduce + gates, 2 outputs per thread
            float hn0, cn0, hn1, cn1;
            {
                float a0 = 0.f, a1 = 0.f, a2 = 0.f, a3 = 0.f;
                float b0 = 0.f, b1 = 0.f, b2 = 0.f, b3 = 0.f;
                #pragma unroll
                for (int k2 = 0; k2 < 2; k2++) {
                    float4 vh0 = redH[((k2 * 4 + r_wm0) * 32 + r_lane) * RED_NP + r_p];
                    float4 vx0 = redX[((k2 * 4 + r_wm0) * 32 + r_lane) * RED_NP + r_p];
                    float4 vh1 = redH[((k2 * 4 + r_wm1) * 32 + r_lane) * RED_NP + r_p];
                    float4 vx1 = redX[((k2 * 4 + r_wm1) * 32 + r_lane) * RED_NP + r_p];
                    a0 += vh0.x + vx0.x; a1 += vh0.y + vx0.y;
                    a2 += vh0.z + vx0.z; a3 += vh0.w + vx0.w;
                    b0 += vh1.x + vx1.x; b1 += vh1.y + vx1.y;
                    b2 += vh1.z + vx1.z; b3 += vh1.w + vx1.w;
                }
                cn0 = sigmf(a0 + bias0) * creg0 + sigmf(a1 + bias1) * tanhf(a2 + bias2);
                creg0 = cn0;
                hn0 = sigmf(a3 + bias3) * tanhf(cn0);
                cn1 = sigmf(b0 + bias0) * creg1 + sigmf(b1 + bias1) * tanhf(b2 + bias2);
                creg1 = cn1;
                hn1 = sigmf(b3 + bias3) * tanhf(cn1);
                st_h_cg(hw + hidx0, __float2half_rn(hn0));
                st_h_cg(hw + hidx1, __float2half_rn(hn1));
            }
            BARH();                                       // all h stores done

            if (tid == 0) {
                unsigned gen = (unsigned)(s + 1);
                unsigned t = atom_add_acqrel(&g_cnt1[grp * 32], 1u);
                if (t == gen * 16u - 1u) {
                    unsigned r = atom_add_acqrel(&g_cnt2, 1u);
                    if (r == gen * 8u - 1u)
                        st_rel(&g_gen, gen);
                }
            }

            out_hs[((size_t)rrow * SS + s) * HH + colg] = hn0;
            out_hs[((size_t)(rrow + 32) * SS + s) * HH + colg] = hn1;
            if (s == SS - 1) {
                out[(size_t)rrow * HH + colg] = hn0;
                out[(size_t)(rrow + 32) * HH + colg] = hn1;
                out[(size_t)BB * HH + (size_t)rrow * HH + colg] = cn0;
                out[(size_t)BB * HH + (size_t)(rrow + 32) * HH + colg] = cn1;
            }

            BARJ();                                       // J_s: redX handoff
        }
    } else {
        // ================= xp-group =================
        {   // prologue: xp partials for step 0 -> redX0
            float acc[4][4];
            #pragma unroll
            for (int g = 0; g < 4; g++)
                #pragma unroll
                for (int p = 0; p < 4; p++) acc[g][p] = 0.f;
            const uint2* __restrict__ xb = g_xf;
            GEMM32(xb, __ldg, SM_U_BASE);
            float4* dst4 = redX0 + (wq * 32 + lane) * RED_NP;
            #pragma unroll
            for (int p = 0; p < 4; p++)
                dst4[p] = make_float4(acc[0][p], acc[1][p], acc[2][p], acc[3][p]);
        }
        BARJ();

        for (int s = 0; s < SS; s++) {
            if (s + 1 < SS) {
                float acc[4][4];
                #pragma unroll
                for (int g = 0; g < 4; g++)
                    #pragma unroll
                    for (int p = 0; p < 4; p++) acc[g][p] = 0.f;
                const uint2* __restrict__ xb = g_xf + (size_t)(s + 1) * 16384;
                GEMM32(xb, __ldg, SM_U_BASE);
                float4* dst4 = (((s + 1) & 1) ? redX1 : redX0) + (wq * 32 + lane) * RED_NP;
                #pragma unroll
                for (int p = 0; p < 4; p++)
                    dst4[p] = make_float4(acc[0][p], acc[1][p], acc[2][p], acc[3][p]);
            }
            BARJ();                                       // J_s
        }
    }
    #undef GEMM32
}

// ---------------- launch ----------------
extern "C" void kernel_launch(void* const* d_in, const int* in_sizes, int n_in,
                              void* d_out, int out_size)
{
    const float* x  = (const float*)d_in[0];
    const float* Uf = (const float*)d_in[1];
    const float* Ui = (const float*)d_in[2];
    const float* Uc = (const float*)d_in[3];
    const float* Uo = (const float*)d_in[4];
    const float* Wf = (const float*)d_in[5];
    const float* Wi = (const float*)d_in[6];
    const float* Wc = (const float*)d_in[7];
    const float* Wo = (const float*)d_in[8];
    const float* bf = (const float*)d_in[9];
    const float* bi = (const float*)d_in[10];
    const float* bc = (const float*)d_in[11];
    const float* bo = (const float*)d_in[12];
    float* out = (float*)d_out;

    static int smem_set = 0;
    if (!smem_set) {
        cudaFuncSetAttribute(lstm_persistent,
                             cudaFuncAttributeMaxDynamicSharedMemorySize, SM_TOTAL);
        smem_set = 1;
    }

    pack_kernel<<<dim3(32, 32, 8), dim3(32, 8)>>>(Uf, Ui, Uc, Uo, Wf, Wi, Wc, Wo);
    xconv_kernel<<<(SS * 16384) / 256, 256>>>(x);     // 2^23 jobs, 1 uint2 each
    init_kernel<<<(32768 + 255) / 256, 256>>>();

    float* hs = out + 2 * BB * HH;   // hidden_seq region
    lstm_persistent<<<NCTA, PTHR, SM_TOTAL>>>(out, hs, bf, bi, bc, bo);
}

// round 16
// speedup vs baseline: 1.1544x; 1.1544x over previous
#include <cuda_runtime.h>
#include <cuda_fp16.h>

#define BB 64
#define SS 512
#define II 1024
#define HH 1024
#define NG 4096          // 4*H
#define MMR (BB*SS)      // 32768
#define NCTA 128
#define PTHR 512

// ---------------- device scratch (no allocs allowed) ----------------
__device__ __align__(16) __half g_Uph[(size_t)NG * II];     // U_all^T [n][k], fp16
__device__ __align__(16) __half g_Wph[(size_t)NG * HH];     // W_all^T [n][k], fp16
// x fp16 in a-fragment order per step: uint2 g_xf[s][ (kk16*64 + row)*4 + tq ]
__device__ __align__(16) uint2 g_xf[(size_t)SS * 16384];
// h fp16 in a-fragment order (same convention), double buffered
__device__ __align__(16) unsigned g_hf[2][32768];
// two-level grid barrier: 8 group counters (128B-strided) -> root -> broadcast gen
__device__ unsigned g_cnt1[8 * 32];
__device__ unsigned g_cnt2;
__device__ unsigned g_gen;

// ---------------- helpers ----------------
__device__ __forceinline__ unsigned h2pack(float lo, float hi) {
    unsigned u;
    asm("cvt.rn.f16x2.f32 %0, %1, %2;" : "=r"(u) : "f"(hi), "f"(lo));
    return u;
}

__device__ __forceinline__ void mma16(float* d, const unsigned* a, unsigned b0, unsigned b1) {
    asm volatile(
        "mma.sync.aligned.m16n8k16.row.col.f32.f16.f16.f32 "
        "{%0,%1,%2,%3}, {%4,%5,%6,%7}, {%8,%9}, {%0,%1,%2,%3};"
        : "+f"(d[0]), "+f"(d[1]), "+f"(d[2]), "+f"(d[3])
        : "r"(a[0]), "r"(a[1]), "r"(a[2]), "r"(a[3]), "r"(b0), "r"(b1));
}

// fast activations (MUFU-based; rel err ~1e-6, negligible vs 3e-4 budget)
__device__ __forceinline__ float sigmf(float x) {
    return __fdividef(1.f, 1.f + __expf(-x));
}
__device__ __forceinline__ float tanhfast(float x) {
    return 1.f - 2.f * __fdividef(1.f, __expf(2.f * x) + 1.f);
}

__device__ __forceinline__ void st_h_cg(__half* p, __half v) {
    unsigned short s = __half_as_ushort(v);
    asm volatile("st.global.cg.u16 [%0], %1;" :: "l"(p), "h"(s) : "memory");
}

__device__ __forceinline__ unsigned ld_acq(const unsigned* p) {
    unsigned v;
    asm volatile("ld.acquire.gpu.global.u32 %0, [%1];" : "=r"(v) : "l"(p) : "memory");
    return v;
}

__device__ __forceinline__ unsigned atom_add_acqrel(unsigned* p, unsigned v) {
    unsigned old;
    asm volatile("atom.add.acq_rel.gpu.global.u32 %0, [%1], %2;"
                 : "=r"(old) : "l"(p), "r"(v) : "memory");
    return old;
}

__device__ __forceinline__ void st_rel(unsigned* p, unsigned v) {
    asm volatile("st.release.gpu.global.u32 [%0], %1;" :: "l"(p), "r"(v) : "memory");
}

// ---------------- pack: build K-major fp16 U_all^T / W_all^T ----------------
__global__ void pack_kernel(
    const float* __restrict__ Uf, const float* __restrict__ Ui,
    const float* __restrict__ Uc, const float* __restrict__ Uo,
    const float* __restrict__ Wf, const float* __restrict__ Wi,
    const float* __restrict__ Wc, const float* __restrict__ Wo)
{
    __shared__ float t[32][33];
    int z = blockIdx.z;
    int g = z & 3;
    const float* src;
    __half* dst;
    if (z < 4) { src = (g == 0) ? Uf : (g == 1) ? Ui : (g == 2) ? Uc : Uo; dst = g_Uph; }
    else       { src = (g == 0) ? Wf : (g == 1) ? Wi : (g == 2) ? Wc : Wo; dst = g_Wph; }
    int n0 = blockIdx.x * 32, k0 = blockIdx.y * 32;
    int tx = threadIdx.x, ty = threadIdx.y;   // 32 x 8
    #pragma unroll
    for (int i = 0; i < 4; i++) {
        int kr = ty + i * 8;
        t[kr][tx] = src[(size_t)(k0 + kr) * HH + n0 + tx];
    }
    __syncthreads();
    #pragma unroll
    for (int i = 0; i < 4; i++) {
        int nr = ty + i * 8;
        dst[(size_t)(g * HH + n0 + nr) * II + k0 + tx] = __float2half_rn(t[tx][nr]);
    }
}

// ---------------- x fp32 -> fp16 a-fragment order ----------------
// Job space: SS*16384 = 2^23 jobs, one uint2 each. idx bits: tq(2)|row(6)|kk(6)|s(9)
__global__ void xconv_kernel(const float* __restrict__ x) {
    int idx = blockIdx.x * 256 + threadIdx.x;
    if (idx >= SS * 16384) return;
    int tq  = idx & 3;
    int row = (idx >> 2) & 63;
    int kk  = (idx >> 8) & 63;
    int s   = idx >> 14;
    const float* xr = x + ((size_t)row * SS + s) * II + kk * 16;
    float2 lo = *(const float2*)(xr + 2 * tq);
    float2 hi = *(const float2*)(xr + 2 * tq + 8);
    g_xf[(size_t)s * 16384 + (kk * 64 + row) * 4 + tq] =
        make_uint2(h2pack(lo.x, lo.y), h2pack(hi.x, hi.y));
}

__global__ void init_kernel() {
    int i = blockIdx.x * blockDim.x + threadIdx.x;
    if (i < 32768) g_hf[0][i] = 0u;
    if (i < 8 * 32) g_cnt1[i] = 0u;
    if (i == 0) { g_cnt2 = 0u; g_gen = 0u; }
}

// ---------------- fused persistent kernel ----------------
// 128 CTAs x 512 thr (16 warps = 4 m-slabs(16 rows) x 4 K-splits(256)). CTA j owns
// hidden cols [8j,8j+8). W/U fp16 SMEM (64KB each), swizzled. xp partials for step
// s+1 are computed in barrier slack and CARRIED IN acc REGISTERS into step s+1's
// h-GEMM -> one combined dump+reduce per step. acq_rel barrier chain (no membar).
#define SM_W_BYTES   65536
#define SM_U_BASE    65536
#define RED_BASE     131072
#define RED_NP       5                          // float4 slots per (warp,lane), 1 pad
#define SM_RED_BYTES (PTHR * RED_NP * 16)       // 40960
#define SM_TOTAL     (RED_BASE + SM_RED_BYTES)  // 172032

__global__ __launch_bounds__(PTHR, 1) void lstm_persistent(
    float* __restrict__ out, float* __restrict__ out_hs,
    const float* __restrict__ bf, const float* __restrict__ bi,
    const float* __restrict__ bc, const float* __restrict__ bo)
{
    extern __shared__ __align__(16) unsigned char sm_raw[];
    float4* red4 = (float4*)(sm_raw + RED_BASE);             // [(w*32+lane)][RED_NP]

    const int tid = threadIdx.x;
    const int lane = tid & 31, w = tid >> 5;
    const int wm = w & 3, kh = w >> 2;        // 4 m-slabs x 4 K-splits
    const int gq = lane >> 2, tq = lane & 3;
    const int j = blockIdx.x;

    // ---- one-time: pack W and U slices into swizzled fp16 fragment layout ----
    #pragma unroll
    for (int src = 0; src < 2; src++) {
        const unsigned* Wp_u = (const unsigned*)(src == 0 ? g_Wph : g_Uph);
        unsigned obase = src == 0 ? 0u : (unsigned)SM_U_BASE;
        #pragma unroll
        for (int t = 0; t < 8; t++) {
            int job = tid + t * PTHR;        // 4096 jobs = 64 kk16 x 32 slots x 2 chunks
            int kk = job >> 6;
            int rem = job & 63;
            int s  = rem >> 1, chunk = rem & 1;
            int sgq = s >> 2, stq = s & 3;
            int gp = chunk * 2;
            const unsigned* W0 = Wp_u + (size_t)(gp * 1024 + j * 8 + sgq) * 512;
            const unsigned* W1 = W0 + 1024 * 512;
            unsigned lo0 = W0[kk * 8 + stq], hi0 = W0[kk * 8 + stq + 4];
            unsigned lo1 = W1[kk * 8 + stq], hi1 = W1[kk * 8 + stq + 4];
            unsigned swz = ((unsigned)(s >> 2) & 1u) * 16u;
            unsigned off = obase + (unsigned)kk * 1024u +
                           (((unsigned)s * 32u + (unsigned)chunk * 16u) ^ swz);
            *(uint4*)(sm_raw + off) = make_uint4(lo0, hi0, lo1, hi1);
        }
    }
    __syncthreads();

    // ---- per-thread epilogue mapping (one (row, cc) output per thread) ----
    const int rrow = tid >> 3, cc = tid & 7;
    const int r_wm = rrow >> 4;                              // m-slab (16 rows)
    const int r_p  = ((rrow >> 3) & 1) * 2 + (cc & 1);
    const int r_lane = (rrow & 7) * 4 + (cc >> 1);
    const int colg = j * 8 + cc;
    const int kkj = j >> 1;
    const int hidx = (((kkj * 64 + rrow) * 4 + (cc >> 1)) * 2 + (j & 1)) * 2 + (cc & 1);

    // per-thread b-frag smem offsets (swizzled)
    const int s_me = gq * 4 + tq;
    const unsigned swz_me = ((unsigned)(s_me >> 2) & 1u) * 16u;
    const unsigned woff0 = (((unsigned)s_me * 32u) ^ swz_me);
    const unsigned woff1 = (((unsigned)s_me * 32u + 16u) ^ swz_me);

    const int grp = j >> 4;                    // barrier group (8 groups of 16)

    const float bias0 = __ldg(bf + colg), bias1 = __ldg(bi + colg);
    const float bias2 = __ldg(bc + colg), bias3 = __ldg(bo + colg);

    float creg = 0.f;
    unsigned gen = 0;

    const int kb16 = kh * 16;                  // this warp's kk16 range (16 slices)
    const int arow = wm * 16 + gq;             // a-frag row

    // hoisted output pointer (advance by HH per step)
    float* hs_ptr = out_hs + (size_t)rrow * SS * HH + colg;

    // acc carries xp partials (for the upcoming step) across the barrier, then the
    // h-GEMM accumulates on top -> one combined reduction.
    float acc[4][4];

    // ================= xp-GEMM into acc (registers only, no syncs) ==============
    #define XP_GEMM(snext)                                                         \
    {                                                                              \
        const uint2* __restrict__ xb = g_xf + (size_t)(snext) * 16384;             \
        _Pragma("unroll")                                                          \
        for (int g = 0; g < 4; g++)                                                \
            _Pragma("unroll")                                                      \
            for (int p = 0; p < 4; p++) acc[g][p] = 0.f;                           \
        uint2 qA[4][2];                                                            \
        _Pragma("unroll")                                                          \
        for (int p = 0; p < 4; p++) {                                              \
            int base = ((kb16 + p) * 64 + arow) * 4 + tq;                          \
            qA[p][0] = __ldg(xb + base);                                           \
            qA[p][1] = __ldg(xb + base + 32);                                      \
        }                                                                          \
        _Pragma("unroll 4")                                                        \
        for (int i = 0; i < 16; i++) {                                             \
            int sl = i & 3;                                                        \
            uint2 u0 = qA[sl][0], u1 = qA[sl][1];                                  \
            if (i < 12) {                                                          \
                int base = ((kb16 + i + 4) * 64 + arow) * 4 + tq;                  \
                qA[sl][0] = __ldg(xb + base);                                      \
                qA[sl][1] = __ldg(xb + base + 32);                                 \
            }                                                                      \
            unsigned a0[4] = { u0.x, u1.x, u0.y, u1.y };                           \
            unsigned wb = (unsigned)SM_U_BASE + (unsigned)(kb16 + i) * 1024u;      \
            uint4 b01 = *(const uint4*)(sm_raw + wb + woff0);                      \
            uint4 b23 = *(const uint4*)(sm_raw + wb + woff1);                      \
            mma16(acc[0], a0, b01.x, b01.y);                                       \
            mma16(acc[1], a0, b01.z, b01.w);                                       \
            mma16(acc[2], a0, b23.x, b23.y);                                       \
            mma16(acc[3], a0, b23.z, b23.w);                                       \
        }                                                                          \
    }
    // ============================================================================

    // prologue: xp partials for step 0
    XP_GEMM(0);

    for (int s = 0; s < SS; s++) {
        const uint2* __restrict__ hb = (const uint2*)g_hf[s & 1];
        __half*      __restrict__ hw = (__half*)g_hf[(s + 1) & 1];

        // h-GEMM accumulates onto xp partials already in acc
        uint2 qA[4][2];
        #pragma unroll
        for (int p = 0; p < 4; p++) {
            int base = ((kb16 + p) * 64 + arow) * 4 + tq;
            qA[p][0] = __ldcg(hb + base);
            qA[p][1] = __ldcg(hb + base + 32);
        }

        #pragma unroll 4
        for (int i = 0; i < 16; i++) {
            int sl = i & 3;
            uint2 u0 = qA[sl][0], u1 = qA[sl][1];
            if (i < 12) {
                int base = ((kb16 + i + 4) * 64 + arow) * 4 + tq;
                qA[sl][0] = __ldcg(hb + base);
                qA[sl][1] = __ldcg(hb + base + 32);
            }
            unsigned a0[4] = { u0.x, u1.x, u0.y, u1.y };
            unsigned wb = (unsigned)(kb16 + i) * 1024u;
            uint4 b01 = *(const uint4*)(sm_raw + wb + woff0);
            uint4 b23 = *(const uint4*)(sm_raw + wb + woff1);
            mma16(acc[0], a0, b01.x, b01.y);
            mma16(acc[1], a0, b01.z, b01.w);
            mma16(acc[2], a0, b23.x, b23.y);
            mma16(acc[3], a0, b23.z, b23.w);
        }

        // combined dump (p-major float4, padded stride)
        {
            float4* dst4 = red4 + (w * 32 + lane) * RED_NP;
            #pragma unroll
            for (int p = 0; p < 4; p++)
                dst4[p] = make_float4(acc[0][p], acc[1][p], acc[2][p], acc[3][p]);
        }
        __syncthreads();

        // combined reduction + gate epilogue (fast activations)
        float hn, cn;
        {
            float gs0 = 0.f, gs1 = 0.f, gs2 = 0.f, gs3 = 0.f;
            #pragma unroll
            for (int kh2 = 0; kh2 < 4; kh2++) {
                float4 v = red4[((kh2 * 4 + r_wm) * 32 + r_lane) * RED_NP + r_p];
                gs0 += v.x; gs1 += v.y; gs2 += v.z; gs3 += v.w;
            }
            float gf = gs0 + bias0;
            float gi = gs1 + bias1;
            float gc = gs2 + bias2;
            float go = gs3 + bias3;
            cn = sigmf(gf) * creg + sigmf(gi) * tanhfast(gc);
            creg = cn;
            hn = sigmf(go) * tanhfast(cn);
            st_h_cg(hw + hidx, __float2half_rn(hn));
        }

        // publish h_{s+1}: syncthreads orders all h stores before tid0's release arrive
        __syncthreads();
        gen++;
        if (tid == 0) {
            unsigned t = atom_add_acqrel(&g_cnt1[grp * 32], 1u);
            if (t == gen * 16u - 1u) {
                unsigned r = atom_add_acqrel(&g_cnt2, 1u);
                if (r == gen * 8u - 1u)
                    st_rel(&g_gen, gen);
            }
        }

        // barrier slack: xp partials for step s+1 (registers only)
        if (s + 1 < SS) {
            XP_GEMM(s + 1);
        }

        // also in slack: hidden_seq store (+ final outputs)
        *hs_ptr = hn;
        hs_ptr += HH;
        if (s == SS - 1) {
            out[(size_t)rrow * HH + colg] = hn;
            out[(size_t)BB * HH + (size_t)rrow * HH + colg] = cn;
        }

        if (tid == 0) {
            while (ld_acq(&g_gen) < gen) { }
        }
        __syncthreads();
    }
    #undef XP_GEMM
}

// ---------------- launch ----------------
extern "C" void kernel_launch(void* const* d_in, const int* in_sizes, int n_in,
                              void* d_out, int out_size)
{
    const float* x  = (const float*)d_in[0];
    const float* Uf = (const float*)d_in[1];
    const float* Ui = (const float*)d_in[2];
    const float* Uc = (const float*)d_in[3];
    const float* Uo = (const float*)d_in[4];
    const float* Wf = (const float*)d_in[5];
    const float* Wi = (const float*)d_in[6];
    const float* Wc = (const float*)d_in[7];
    const float* Wo = (const float*)d_in[8];
    const float* bf = (const float*)d_in[9];
    const float* bi = (const float*)d_in[10];
    const float* bc = (const float*)d_in[11];
    const float* bo = (const float*)d_in[12];
    float* out = (float*)d_out;

    static int smem_set = 0;
    if (!smem_set) {
        cudaFuncSetAttribute(lstm_persistent,
                             cudaFuncAttributeMaxDynamicSharedMemorySize, SM_TOTAL);
        smem_set = 1;
    }

    pack_kernel<<<dim3(32, 32, 8), dim3(32, 8)>>>(Uf, Ui, Uc, Uo, Wf, Wi, Wc, Wo);
    xconv_kernel<<<(SS * 16384) / 256, 256>>>(x);     // 2^23 jobs, 1 uint2 each
    init_kernel<<<(32768 + 255) / 256, 256>>>();

    float* hs = out + 2 * BB * HH;   // hidden_seq region
    lstm_persistent<<<NCTA, PTHR, SM_TOTAL>>>(out, hs, bf, bi, bc, bo);
}

// round 17
// speedup vs baseline: 1.2462x; 1.0795x over previous
#include <cuda_runtime.h>
#include <cuda_fp16.h>

#define BB 64
#define SS 512
#define II 1024
#define HH 1024
#define NG 4096          // 4*H
#define MMR (BB*SS)      // 32768
#define NCTA 128
#define PTHR 512

// ---------------- device scratch (no allocs allowed) ----------------
__device__ __align__(16) __half g_Uph[(size_t)NG * II];     // U_all^T [n][k], fp16
__device__ __align__(16) __half g_Wph[(size_t)NG * HH];     // W_all^T [n][k], fp16
// x fp16 in a-fragment order per step: uint2 g_xf[s][ (kk16*64 + row)*4 + tq ]
__device__ __align__(16) uint2 g_xf[(size_t)SS * 16384];
// h fp16 in a-fragment order (same convention), double buffered
__device__ __align__(16) unsigned g_hf[2][32768];
// two-level grid barrier: 8 group counters (128B-strided) -> root -> broadcast gen
__device__ unsigned g_cnt1[8 * 32];
__device__ unsigned g_cnt2;
__device__ unsigned g_gen;

// ---------------- helpers ----------------
__device__ __forceinline__ unsigned h2pack(float lo, float hi) {
    unsigned u;
    asm("cvt.rn.f16x2.f32 %0, %1, %2;" : "=r"(u) : "f"(hi), "f"(lo));
    return u;
}

__device__ __forceinline__ void mma16(float* d, const unsigned* a, unsigned b0, unsigned b1) {
    asm volatile(
        "mma.sync.aligned.m16n8k16.row.col.f32.f16.f16.f32 "
        "{%0,%1,%2,%3}, {%4,%5,%6,%7}, {%8,%9}, {%0,%1,%2,%3};"
        : "+f"(d[0]), "+f"(d[1]), "+f"(d[2]), "+f"(d[3])
        : "r"(a[0]), "r"(a[1]), "r"(a[2]), "r"(a[3]), "r"(b0), "r"(b1));
}

// fast activations (MUFU-based; rel err ~1e-6, negligible vs 3e-4 budget)
__device__ __forceinline__ float sigmf(float x) {
    return __fdividef(1.f, 1.f + __expf(-x));
}
__device__ __forceinline__ float tanhfast(float x) {
    return 1.f - 2.f * __fdividef(1.f, __expf(2.f * x) + 1.f);
}

__device__ __forceinline__ void st_h_cg(__half* p, __half v) {
    unsigned short s = __half_as_ushort(v);
    asm volatile("st.global.cg.u16 [%0], %1;" :: "l"(p), "h"(s) : "memory");
}

__device__ __forceinline__ unsigned ld_acq(const unsigned* p) {
    unsigned v;
    asm volatile("ld.acquire.gpu.global.u32 %0, [%1];" : "=r"(v) : "l"(p) : "memory");
    return v;
}

__device__ __forceinline__ unsigned atom_add_acqrel(unsigned* p, unsigned v) {
    unsigned old;
    asm volatile("atom.add.acq_rel.gpu.global.u32 %0, [%1], %2;"
                 : "=r"(old) : "l"(p), "r"(v) : "memory");
    return old;
}

__device__ __forceinline__ void st_rel(unsigned* p, unsigned v) {
    asm volatile("st.release.gpu.global.u32 [%0], %1;" :: "l"(p), "r"(v) : "memory");
}

// ---------------- pack: build K-major fp16 U_all^T / W_all^T ----------------
__global__ void pack_kernel(
    const float* __restrict__ Uf, const float* __restrict__ Ui,
    const float* __restrict__ Uc, const float* __restrict__ Uo,
    const float* __restrict__ Wf, const float* __restrict__ Wi,
    const float* __restrict__ Wc, const float* __restrict__ Wo)
{
    __shared__ float t[32][33];
    int z = blockIdx.z;
    int g = z & 3;
    const float* src;
    __half* dst;
    if (z < 4) { src = (g == 0) ? Uf : (g == 1) ? Ui : (g == 2) ? Uc : Uo; dst = g_Uph; }
    else       { src = (g == 0) ? Wf : (g == 1) ? Wi : (g == 2) ? Wc : Wo; dst = g_Wph; }
    int n0 = blockIdx.x * 32, k0 = blockIdx.y * 32;
    int tx = threadIdx.x, ty = threadIdx.y;   // 32 x 8
    #pragma unroll
    for (int i = 0; i < 4; i++) {
        int kr = ty + i * 8;
        t[kr][tx] = src[(size_t)(k0 + kr) * HH + n0 + tx];
    }
    __syncthreads();
    #pragma unroll
    for (int i = 0; i < 4; i++) {
        int nr = ty + i * 8;
        dst[(size_t)(g * HH + n0 + nr) * II + k0 + tx] = __float2half_rn(t[tx][nr]);
    }
}

// ---------------- x fp32 -> fp16 a-fragment order ----------------
// Job space: SS*16384 = 2^23 jobs, one uint2 each. idx bits: tq(2)|row(6)|kk(6)|s(9)
__global__ void xconv_kernel(const float* __restrict__ x) {
    int idx = blockIdx.x * 256 + threadIdx.x;
    if (idx >= SS * 16384) return;
    int tq  = idx & 3;
    int row = (idx >> 2) & 63;
    int kk  = (idx >> 8) & 63;
    int s   = idx >> 14;
    const float* xr = x + ((size_t)row * SS + s) * II + kk * 16;
    float2 lo = *(const float2*)(xr + 2 * tq);
    float2 hi = *(const float2*)(xr + 2 * tq + 8);
    g_xf[(size_t)s * 16384 + (kk * 64 + row) * 4 + tq] =
        make_uint2(h2pack(lo.x, lo.y), h2pack(hi.x, hi.y));
}

__global__ void init_kernel() {
    int i = blockIdx.x * blockDim.x + threadIdx.x;
    if (i < 32768) g_hf[0][i] = 0u;
    if (i < 8 * 32) g_cnt1[i] = 0u;
    if (i == 0) { g_cnt2 = 0u; g_gen = 0u; }
}

// ---------------- fused persistent kernel ----------------
// 128 CTAs x 512 thr (16 warps = 2 m-slabs(32 rows) x 8 K-splits(128)). CTA j owns
// hidden cols [8j,8j+8). W/U fp16 SMEM (64KB each), swizzled; each b-frag pair
// (2x LDS.128) feeds 8 mma (2 m-frags x 4 gates). xp partials for step s+1 are
// computed in barrier slack and carried in acc registers into step s+1's h-GEMM.
#define SM_W_BYTES   65536
#define SM_U_BASE    65536
#define RED_BASE     131072
#define RED_NP       9                          // float4 slots per (warp,lane), 1 pad
#define SM_RED_BYTES (PTHR * RED_NP * 16)       // 73728
#define SM_TOTAL     (RED_BASE + SM_RED_BYTES)  // 204800

__global__ __launch_bounds__(PTHR, 1) void lstm_persistent(
    float* __restrict__ out, float* __restrict__ out_hs,
    const float* __restrict__ bf, const float* __restrict__ bi,
    const float* __restrict__ bc, const float* __restrict__ bo)
{
    extern __shared__ __align__(16) unsigned char sm_raw[];
    float4* red4 = (float4*)(sm_raw + RED_BASE);             // [(w*32+lane)][RED_NP]

    const int tid = threadIdx.x;
    const int lane = tid & 31, w = tid >> 5;
    const int wm = w & 1, kh = w >> 1;        // 2 m-slabs x 8 K-splits
    const int gq = lane >> 2, tq = lane & 3;
    const int j = blockIdx.x;

    // ---- one-time: pack W and U slices into swizzled fp16 fragment layout ----
    #pragma unroll
    for (int src = 0; src < 2; src++) {
        const unsigned* Wp_u = (const unsigned*)(src == 0 ? g_Wph : g_Uph);
        unsigned obase = src == 0 ? 0u : (unsigned)SM_U_BASE;
        #pragma unroll
        for (int t = 0; t < 8; t++) {
            int job = tid + t * PTHR;        // 4096 jobs = 64 kk16 x 32 slots x 2 chunks
            int kk = job >> 6;
            int rem = job & 63;
            int s  = rem >> 1, chunk = rem & 1;
            int sgq = s >> 2, stq = s & 3;
            int gp = chunk * 2;
            const unsigned* W0 = Wp_u + (size_t)(gp * 1024 + j * 8 + sgq) * 512;
            const unsigned* W1 = W0 + 1024 * 512;
            unsigned lo0 = W0[kk * 8 + stq], hi0 = W0[kk * 8 + stq + 4];
            unsigned lo1 = W1[kk * 8 + stq], hi1 = W1[kk * 8 + stq + 4];
            unsigned swz = ((unsigned)(s >> 2) & 1u) * 16u;
            unsigned off = obase + (unsigned)kk * 1024u +
                           (((unsigned)s * 32u + (unsigned)chunk * 16u) ^ swz);
            *(uint4*)(sm_raw + off) = make_uint4(lo0, hi0, lo1, hi1);
        }
    }
    __syncthreads();

    // ---- per-thread epilogue mapping (one (row, cc) output per thread) ----
    const int rrow = tid >> 3, cc = tid & 7;
    const int r_wm = rrow >> 5;                              // m-slab (32 rows)
    const int r_mt = (rrow >> 4) & 1;                        // m-frag within slab
    const int r_p  = ((rrow >> 3) & 1) * 2 + (cc & 1);
    const int r_lane = (rrow & 7) * 4 + (cc >> 1);
    const int colg = j * 8 + cc;
    const int kkj = j >> 1;
    const int hidx = (((kkj * 64 + rrow) * 4 + (cc >> 1)) * 2 + (j & 1)) * 2 + (cc & 1);

    // per-thread b-frag smem offsets (swizzled)
    const int s_me = gq * 4 + tq;
    const unsigned swz_me = ((unsigned)(s_me >> 2) & 1u) * 16u;
    const unsigned woff0 = (((unsigned)s_me * 32u) ^ swz_me);
    const unsigned woff1 = (((unsigned)s_me * 32u + 16u) ^ swz_me);

    const int grp = j >> 4;                    // barrier group (8 groups of 16)

    const float bias0 = __ldg(bf + colg), bias1 = __ldg(bi + colg);
    const float bias2 = __ldg(bc + colg), bias3 = __ldg(bo + colg);

    float creg = 0.f;
    unsigned gen = 0;

    const int kb16 = kh * 8;                   // this warp's kk16 range (8 slices)
    const int arow = wm * 32 + gq;             // base a-frag row (covers +0,+8,+16,+24)

    // hoisted output pointer (advance by HH per step)
    float* hs_ptr = out_hs + (size_t)rrow * SS * HH + colg;

    // acc carries xp partials (for the upcoming step) across the barrier, then the
    // h-GEMM accumulates on top -> one combined reduction. [mt][gate][p]
    float acc[2][4][4];

    // ===== GEMM over this warp's 8 slices, both m-frags, depth-2 prefetch =======
    #define GEMM8(XB, LDFN, WBASE)                                                 \
    {                                                                              \
        uint2 qA[2][4];                                                            \
        _Pragma("unroll")                                                          \
        for (int p = 0; p < 2; p++) {                                              \
            int base = ((kb16 + p) * 64 + arow) * 4 + tq;                          \
            qA[p][0] = LDFN((XB) + base);                                          \
            qA[p][1] = LDFN((XB) + base + 32);                                     \
            qA[p][2] = LDFN((XB) + base + 64);                                     \
            qA[p][3] = LDFN((XB) + base + 96);                                     \
        }                                                                          \
        _Pragma("unroll")                                                          \
        for (int i = 0; i < 8; i++) {                                              \
            int sl = i & 1;                                                        \
            uint2 u0 = qA[sl][0], u1 = qA[sl][1], u2 = qA[sl][2], u3 = qA[sl][3];  \
            if (i < 6) {                                                           \
                int base = ((kb16 + i + 2) * 64 + arow) * 4 + tq;                  \
                qA[sl][0] = LDFN((XB) + base);                                     \
                qA[sl][1] = LDFN((XB) + base + 32);                                \
                qA[sl][2] = LDFN((XB) + base + 64);                                \
                qA[sl][3] = LDFN((XB) + base + 96);                                \
            }                                                                      \
            unsigned a0[4] = { u0.x, u1.x, u0.y, u1.y };                           \
            unsigned a1[4] = { u2.x, u3.x, u2.y, u3.y };                           \
            unsigned wb = (unsigned)(WBASE) + (unsigned)(kb16 + i) * 1024u;        \
            uint4 b01 = *(const uint4*)(sm_raw + wb + woff0);                      \
            uint4 b23 = *(const uint4*)(sm_raw + wb + woff1);                      \
            mma16(acc[0][0], a0, b01.x, b01.y);                                    \
            mma16(acc[0][1], a0, b01.z, b01.w);                                    \
            mma16(acc[0][2], a0, b23.x, b23.y);                                    \
            mma16(acc[0][3], a0, b23.z, b23.w);                                    \
            mma16(acc[1][0], a1, b01.x, b01.y);                                    \
            mma16(acc[1][1], a1, b01.z, b01.w);                                    \
            mma16(acc[1][2], a1, b23.x, b23.y);                                    \
            mma16(acc[1][3], a1, b23.z, b23.w);                                    \
        }                                                                          \
    }
    #define ACC_ZERO()                                                             \
        _Pragma("unroll")                                                          \
        for (int mt = 0; mt < 2; mt++)                                             \
            _Pragma("unroll")                                                      \
            for (int g = 0; g < 4; g++)                                            \
                _Pragma("unroll")                                                  \
                for (int p = 0; p < 4; p++) acc[mt][g][p] = 0.f;
    // ============================================================================

    // prologue: xp partials for step 0
    ACC_ZERO();
    GEMM8(g_xf, __ldg, SM_U_BASE);

    for (int s = 0; s < SS; s++) {
        const uint2* __restrict__ hb = (const uint2*)g_hf[s & 1];
        __half*      __restrict__ hw = (__half*)g_hf[(s + 1) & 1];

        // h-GEMM accumulates onto xp partials already in acc
        GEMM8(hb, __ldcg, 0u);

        // combined dump: 8 float4 per thread ([mt][p], gates packed in float4)
        {
            float4* dst4 = red4 + (w * 32 + lane) * RED_NP;
            #pragma unroll
            for (int mt = 0; mt < 2; mt++)
                #pragma unroll
                for (int p = 0; p < 4; p++)
                    dst4[mt * 4 + p] = make_float4(acc[mt][0][p], acc[mt][1][p],
                                                   acc[mt][2][p], acc[mt][3][p]);
        }
        __syncthreads();

        // combined reduction (8 K-splits) + gate epilogue (fast activations)
        float hn, cn;
        {
            float gs0 = 0.f, gs1 = 0.f, gs2 = 0.f, gs3 = 0.f;
            #pragma unroll
            for (int kh2 = 0; kh2 < 8; kh2++) {
                float4 v = red4[((kh2 * 2 + r_wm) * 32 + r_lane) * RED_NP + r_mt * 4 + r_p];
                gs0 += v.x; gs1 += v.y; gs2 += v.z; gs3 += v.w;
            }
            float gf = gs0 + bias0;
            float gi = gs1 + bias1;
            float gc = gs2 + bias2;
            float go = gs3 + bias3;
            cn = sigmf(gf) * creg + sigmf(gi) * tanhfast(gc);
            creg = cn;
            hn = sigmf(go) * tanhfast(cn);
            st_h_cg(hw + hidx, __float2half_rn(hn));
        }

        // publish h_{s+1}: syncthreads orders all h stores before tid0's release arrive
        __syncthreads();
        gen++;
        if (tid == 0) {
            unsigned t = atom_add_acqrel(&g_cnt1[grp * 32], 1u);
            if (t == gen * 16u - 1u) {
                unsigned r = atom_add_acqrel(&g_cnt2, 1u);
                if (r == gen * 8u - 1u)
                    st_rel(&g_gen, gen);
            }
        }

        // barrier slack: xp partials for step s+1 (registers only)
        ACC_ZERO();
        if (s + 1 < SS) {
            const uint2* __restrict__ xb = g_xf + (size_t)(s + 1) * 16384;
            GEMM8(xb, __ldg, SM_U_BASE);
        }

        // also in slack: hidden_seq store (+ final outputs)
        *hs_ptr = hn;
        hs_ptr += HH;
        if (s == SS - 1) {
            out[(size_t)rrow * HH + colg] = hn;
            out[(size_t)BB * HH + (size_t)rrow * HH + colg] = cn;
        }

        if (tid == 0) {
            while (ld_acq(&g_gen) < gen) { }
        }
        __syncthreads();
    }
    #undef GEMM8
    #undef ACC_ZERO
}

// ---------------- launch ----------------
extern "C" void kernel_launch(void* const* d_in, const int* in_sizes, int n_in,
                              void* d_out, int out_size)
{
    const float* x  = (const float*)d_in[0];
    const float* Uf = (const float*)d_in[1];
    const float* Ui = (const float*)d_in[2];
    const float* Uc = (const float*)d_in[3];
    const float* Uo = (const float*)d_in[4];
    const float* Wf = (const float*)d_in[5];
    const float* Wi = (const float*)d_in[6];
    const float* Wc = (const float*)d_in[7];
    const float* Wo = (const float*)d_in[8];
    const float* bf = (const float*)d_in[9];
    const float* bi = (const float*)d_in[10];
    const float* bc = (const float*)d_in[11];
    const float* bo = (const float*)d_in[12];
    float* out = (float*)d_out;

    static int smem_set = 0;
    if (!smem_set) {
        cudaFuncSetAttribute(lstm_persistent,
                             cudaFuncAttributeMaxDynamicSharedMemorySize, SM_TOTAL);
        smem_set = 1;
    }

    pack_kernel<<<dim3(32, 32, 8), dim3(32, 8)>>>(Uf, Ui, Uc, Uo, Wf, Wi, Wc, Wo);
    xconv_kernel<<<(SS * 16384) / 256, 256>>>(x);     // 2^23 jobs, 1 uint2 each
    init_kernel<<<(32768 + 255) / 256, 256>>>();

    float* hs = out + 2 * BB * HH;   // hidden_seq region
    lstm_persistent<<<NCTA, PTHR, SM_TOTAL>>>(out, hs, bf, bi, bc, bo);
}